// round 2
// baseline (speedup 1.0000x reference)
#include <cuda_runtime.h>

// Persistent global accumulators. Zero at module load; area_kernel re-zeroes
// them after consuming, so every kernel_launch sees zeros (graph-replay safe).
__device__ unsigned g_all[32];
__device__ unsigned g_true[32];

// Logit boundaries B[k] = log((k/30)/(1-k/30)), hardcoded (f32-exact to 9 sig
// digits). B[0] = -inf sentinel, B[30] = cutoff where sigmoid_f32(x) == 1.0f.
__constant__ float cB[32] = {
    -3.0e38f,
    -3.36729583f, -2.63905733f, -2.19722458f, -1.87180218f, -1.60943791f,
    -1.38629436f, -1.18958407f, -1.01160091f, -0.84729786f, -0.69314718f,
    -0.54654371f, -0.40546511f, -0.26826399f, -0.13353139f,  0.0f,
     0.13353139f,  0.26826399f,  0.40546511f,  0.54654371f,  0.69314718f,
     0.84729786f,  1.01160091f,  1.18958407f,  1.38629436f,  1.60943791f,
     1.87180218f,  2.19722458f,  2.63905733f,  3.36729583f,
    17.33f, 3.0e38f
};

#define THREADS 256

// Per-element: guess bin j via 30*sigmoid(x) = 15*tanh(x/2)+15 (tanh.approx),
// quantized to 0.25 with the 2^21 magic constant; one exact logit-space
// compare x >= B[j] resolves the true bin in {j-1, j}. Counter address is
// computed arithmetically: addr = bH + j*512 + (p ? 512 : 0), bH pre-biased
// by (tid*2 - 512), so the bin integer never materializes in the hot path.
__device__ __forceinline__ void proc(float x, bool isTrue,
                                     const char* bB, char* bH, unsigned* sT) {
    float r;
    asm("tanh.approx.f32 %0, %1;" : "=f"(r) : "f"(x * 0.5f));
    float y = fmaf(r, 15.0f, 2097167.25f);        // 2^21 + 15.25
    unsigned bits = __float_as_uint(y);
    unsigned t = bits & 0xFCu;                     // j*4, j in [0,30]
    // transposed boundary table: entry (j, lane) at bank == lane -> conflict-free
    float U = *(const float*)(bB + (t << 5));
    bool p = (x >= U);
    unsigned short* cp = (unsigned short*)(bH + (t << 7) + (p ? 512u : 0u));
    *cp = (unsigned short)(*cp + 1);
    if (isTrue) {                                  // ~1 in 64 elements
        int bin = (int)(t >> 2) - 1 + (p ? 1 : 0);
        atomicAdd(&sT[bin], 1u);
    }
}

__global__ void __launch_bounds__(THREADS)
hist_kernel(const float4* __restrict__ in4, const int* __restrict__ target, int n4) {
    __shared__ unsigned short sH[32 * THREADS];   // 16 KB private per-thread hists
    __shared__ float sBt[32 * 32];                // boundary table, [j][lane]
    __shared__ unsigned sT[32];

    const int tid = threadIdx.x;
    const int lane = tid & 31;
    if (tid < 32) sT[tid] = 0u;
    for (int idx = tid; idx < 1024; idx += THREADS)
        sBt[idx] = cB[idx >> 5];                  // sBt[j*32+lane] = B[j]
#pragma unroll
    for (int k = 0; k < 16; k++)
        ((unsigned*)sH)[tid + THREADS * k] = 0u;
    __syncthreads();

    const char* bB = (const char*)sBt + lane * 4;
    char* bH = (char*)sH + tid * 2 - 512;

    const int stride = gridDim.x * THREADS;
    for (int i = blockIdx.x * THREADS + tid; i < n4; i += stride) {
        float4 v = __ldcs(in4 + i);               // single-pass streaming
        int tt = __ldg(target + (i >> 4)) - ((i & 15) << 2);
        proc(v.x, tt == 0, bB, bH, sT);
        proc(v.y, tt == 1, bB, bH, sT);
        proc(v.z, tt == 2, bB, bH, sT);
        proc(v.w, tt == 3, bB, bH, sT);
    }
    __syncthreads();

    // Flush: 8 threads per bin, each sums 16 u32 words (= 32 u16 counters),
    // shuffle-reduce the 8 partials, leader -> one global atomic per bin.
    {
        int bin = tid >> 3, part = tid & 7;
        const unsigned* rowp = (const unsigned*)(sH + bin * THREADS);
        unsigned s = 0;
#pragma unroll
        for (int w = 0; w < 16; w++) {
            unsigned v = rowp[part * 16 + w];
            s += (v & 0xFFFFu) + (v >> 16);
        }
        s += __shfl_down_sync(0xFFFFFFFFu, s, 4);
        s += __shfl_down_sync(0xFFFFFFFFu, s, 2);
        s += __shfl_down_sync(0xFFFFFFFFu, s, 1);
        if (part == 0 && s) atomicAdd(&g_all[bin], s);
    }
    if (tid < 32 && sT[tid]) atomicAdd(&g_true[tid], sT[tid]);
}

// Epilogue: reference cumsum/trapezoid math in double, then re-zero the
// global accumulators so the next (graph-replayed) launch starts clean.
__global__ void area_kernel(float* out) {
    if (threadIdx.x != 0 || blockIdx.x != 0) return;
    double ht[31], ha[31];
    double trues = 0.0, total = 0.0;
    for (int b = 0; b < 31; b++) {
        ht[b] = (double)g_true[b];
        ha[b] = (double)g_all[b];
        trues += ht[b];
        total += ha[b];
    }
    double falses = total - trues;
    double tpr[30], fpr[30];
    double ct = 0.0, cf = 0.0;
    for (int i = 0; i < 30; i++) {
        ct += ht[i];
        cf += (ha[i] - ht[i]);
        tpr[29 - i] = (trues - ct) / (trues + 1e-8);
        fpr[29 - i] = (falses - cf) / (falses + 1e-8);
    }
    double area = 0.0, pt = 0.0, pf = 0.0;
    for (int i = 0; i < 30; i++) {
        double w = fabs(fpr[i] - pf);
        area += w * 0.5 * (tpr[i] + pt);
        pt = tpr[i];
        pf = fpr[i];
    }
    out[0] = (float)area;
    for (int b = 0; b < 32; b++) { g_all[b] = 0u; g_true[b] = 0u; }
}

extern "C" void kernel_launch(void* const* d_in, const int* in_sizes, int n_in,
                              void* d_out, int out_size) {
    const float* outp = (const float*)d_in[0];
    const int* target = (const int*)d_in[1];
    int total = in_sizes[0];      // 32,000,000
    int n4 = total / 4;

    int blocks = 148 * 8;         // 2048 threads/SM, 20.4 KB smem/block
    hist_kernel<<<blocks, THREADS>>>((const float4*)outp, target, n4);
    area_kernel<<<1, 1>>>((float*)d_out);
}